// round 1
// baseline (speedup 1.0000x reference)
#include <cuda_runtime.h>
#include <cuda_bf16.h>
#include <math.h>

// Problem constants (fixed by the dataset)
#define EMBED 128
#define HID   128
#define HEADS 4
#define HHID  (HEADS * HID)      // 512
#define MAXN  50000
#define MAXM  50000
#define MAXE  400000

// ---------------------------------------------------------------------------
// Scratch (static __device__ globals; no allocation allowed)
// ---------------------------------------------------------------------------
__device__ __align__(16) float g_hs[MAXN * HHID];       // gelu-pre src hidden
__device__ __align__(16) float g_ht[MAXM * HHID];       // gelu-pre tgt hidden
__device__ __align__(16) float g_ms[MAXN * EMBED];      // messages per source node
__device__ __align__(16) float g_agg[MAXM * EMBED];     // aggregated messages
__device__ __align__(16) float g_logits[MAXE * 4];      // per-edge per-head logits / ex
__device__ int g_counts[MAXM];
__device__ int g_cursor[MAXM];
__device__ int g_offsets[MAXM + 1];
__device__ int g_sorted[MAXE];

// ---------------------------------------------------------------------------
// small helpers
// ---------------------------------------------------------------------------
__device__ __forceinline__ float gelu_exact(float x) {
    return 0.5f * x * (1.0f + erff(x * 0.70710678118654752440f));
}

__device__ __forceinline__ void fma_f32x2(unsigned long long& d,
                                          unsigned long long a,
                                          unsigned long long b) {
    asm("fma.rn.f32x2 %0, %1, %2, %0;" : "+l"(d) : "l"(a), "l"(b));
}

// ---------------------------------------------------------------------------
// CSR build: hist -> scan -> scatter
// ---------------------------------------------------------------------------
__global__ void zero2_kernel(int* a, int* b, int n) {
    int i = blockIdx.x * blockDim.x + threadIdx.x;
    if (i < n) { a[i] = 0; b[i] = 0; }
}

__global__ void hist_kernel(const int* __restrict__ etgt, int* __restrict__ counts, int E) {
    int i = blockIdx.x * blockDim.x + threadIdx.x;
    if (i < E) atomicAdd(&counts[etgt[i]], 1);
}

__global__ void scan_kernel(const int* __restrict__ counts, int* __restrict__ offsets, int M) {
    __shared__ int sm[1024];
    __shared__ int carry;
    int t = threadIdx.x;
    if (t == 0) carry = 0;
    __syncthreads();
    for (int base = 0; base < M; base += 1024) {
        int i = base + t;
        int v = (i < M) ? counts[i] : 0;
        sm[t] = v;
        __syncthreads();
        #pragma unroll
        for (int off = 1; off < 1024; off <<= 1) {
            int x = (t >= off) ? sm[t - off] : 0;
            __syncthreads();
            sm[t] += x;
            __syncthreads();
        }
        if (i < M) offsets[i] = carry + sm[t] - v;
        __syncthreads();
        if (t == 1023) carry += sm[1023];
        __syncthreads();
    }
    if (t == 0) offsets[M] = carry;
}

__global__ void scatter_kernel(const int* __restrict__ etgt,
                               const int* __restrict__ offsets,
                               int* __restrict__ cursor,
                               int* __restrict__ sorted, int E) {
    int i = blockIdx.x * blockDim.x + threadIdx.x;
    if (i < E) {
        int tg = etgt[i];
        int pos = offsets[tg] + atomicAdd(&cursor[tg], 1);
        sorted[pos] = i;
    }
}

// ---------------------------------------------------------------------------
// GEMM: C[rows, ncols] = A[rows,128] @ B[128,ncols] + bias
// 128x128 tile, K=128 resident in smem, 256 threads, 8x8 per thread,
// packed fma.rn.f32x2 inner product.
// ---------------------------------------------------------------------------
#define GEMM_LDA 132
#define GEMM_SMEM_BYTES ((128 * GEMM_LDA + 128 * 128) * 4)

extern __shared__ float s_gemm[];

__global__ void __launch_bounds__(256, 1)
gemm128_kernel(const float* __restrict__ A, const float* __restrict__ B,
               const float* __restrict__ bias, float* __restrict__ C,
               int rows, int ncols) {
    float* As = s_gemm;                  // [128][132]
    float* Bs = s_gemm + 128 * GEMM_LDA; // [128][128]
    int row0 = blockIdx.x * 128;
    int col0 = blockIdx.y * 128;
    int tid = threadIdx.x;

    // fill A tile (guard rows)
    for (int idx = tid; idx < 128 * 32; idx += 256) {
        int r = idx >> 5, c4 = idx & 31;
        float4 v = make_float4(0.f, 0.f, 0.f, 0.f);
        int gr = row0 + r;
        if (gr < rows) v = *(const float4*)(A + (long)gr * 128 + c4 * 4);
        *(float4*)(As + r * GEMM_LDA + c4 * 4) = v;
    }
    // fill B tile (ncols always multiple of 128)
    for (int idx = tid; idx < 128 * 32; idx += 256) {
        int k = idx >> 5, c4 = idx & 31;
        float4 v = *(const float4*)(B + (long)k * ncols + col0 + c4 * 4);
        *(float4*)(Bs + k * 128 + c4 * 4) = v;
    }
    __syncthreads();

    int tx = tid & 15, ty = tid >> 4;
    int r0 = ty * 8, c0 = tx * 8;

    unsigned long long acc[8][4];
    #pragma unroll
    for (int i = 0; i < 8; i++)
        #pragma unroll
        for (int j = 0; j < 4; j++) acc[i][j] = 0ull;

    #pragma unroll 4
    for (int k = 0; k < 128; k++) {
        ulonglong2 b01 = *(const ulonglong2*)(Bs + k * 128 + c0);
        ulonglong2 b23 = *(const ulonglong2*)(Bs + k * 128 + c0 + 4);
        unsigned long long bb0 = b01.x, bb1 = b01.y, bb2 = b23.x, bb3 = b23.y;
        #pragma unroll
        for (int i = 0; i < 8; i++) {
            float a = As[(r0 + i) * GEMM_LDA + k];
            unsigned long long aa;
            asm("mov.b64 %0, {%1, %1};" : "=l"(aa) : "f"(a));
            fma_f32x2(acc[i][0], aa, bb0);
            fma_f32x2(acc[i][1], aa, bb1);
            fma_f32x2(acc[i][2], aa, bb2);
            fma_f32x2(acc[i][3], aa, bb3);
        }
    }

    #pragma unroll
    for (int i = 0; i < 8; i++) {
        int gr = row0 + r0 + i;
        if (gr < rows) {
            #pragma unroll
            for (int j = 0; j < 4; j++) {
                float lo, hi;
                asm("mov.b64 {%0, %1}, %2;" : "=f"(lo), "=f"(hi) : "l"(acc[i][j]));
                int gc = col0 + c0 + j * 2;
                float2 o;
                o.x = lo + bias[gc];
                o.y = hi + bias[gc + 1];
                *(float2*)(C + (long)gr * ncols + gc) = o;
            }
        }
    }
}

// ---------------------------------------------------------------------------
// Edge attention kernel: one warp per target node.
// pass1: logits (gather hs, ht in regs), running max
// pass2: ex = exp(l - mx), den (lane-parallel over edges)
// pass3: weighted message accumulation, single store per target
// ---------------------------------------------------------------------------
__global__ void __launch_bounds__(256)
edge_attn_kernel(const int* __restrict__ sorted,
                 const int* __restrict__ offsets,
                 const int* __restrict__ edge_sources,
                 const float4* __restrict__ hs4,
                 const float4* __restrict__ ht4,
                 const float4* __restrict__ ms4,
                 const float4* __restrict__ aw4,   // attn_w [4][128] as float4
                 float4* __restrict__ logits4,
                 float4* __restrict__ agg4,
                 int M) {
    int warp = (blockIdx.x * blockDim.x + threadIdx.x) >> 5;
    int lane = threadIdx.x & 31;
    if (warp >= M) return;
    int tgt = warp;
    int beg = offsets[tgt], end = offsets[tgt + 1];

    float4 htv[4], aw[4];
    #pragma unroll
    for (int q = 0; q < 4; q++) {
        htv[q] = ht4[(long)tgt * 128 + lane + 32 * q];
        aw[q] = aw4[q * 32 + lane];
    }

    float mx[4] = {-3.4e38f, -3.4e38f, -3.4e38f, -3.4e38f};

    // pass 1: logits
    for (int p = beg; p < end; p++) {
        int e = sorted[p];
        int s = edge_sources[e];
        float part[4];
        #pragma unroll
        for (int q = 0; q < 4; q++) {
            float4 h = hs4[(long)s * 128 + lane + 32 * q];
            float x0 = gelu_exact(h.x + htv[q].x);
            float x1 = gelu_exact(h.y + htv[q].y);
            float x2 = gelu_exact(h.z + htv[q].z);
            float x3 = gelu_exact(h.w + htv[q].w);
            part[q] = x0 * aw[q].x + x1 * aw[q].y + x2 * aw[q].z + x3 * aw[q].w;
        }
        #pragma unroll
        for (int q = 0; q < 4; q++) {
            #pragma unroll
            for (int o = 16; o > 0; o >>= 1)
                part[q] += __shfl_xor_sync(0xffffffffu, part[q], o);
            mx[q] = fmaxf(mx[q], part[q]);
        }
        if (lane == 0)
            logits4[p] = make_float4(part[0], part[1], part[2], part[3]);
    }
    __syncwarp();

    // pass 2: ex + den (distributed over lanes)
    float den[4] = {0.f, 0.f, 0.f, 0.f};
    for (int p = beg + lane; p < end; p += 32) {
        float4 lg = logits4[p];
        float4 ex;
        ex.x = expf(lg.x - mx[0]);
        ex.y = expf(lg.y - mx[1]);
        ex.z = expf(lg.z - mx[2]);
        ex.w = expf(lg.w - mx[3]);
        den[0] += ex.x; den[1] += ex.y; den[2] += ex.z; den[3] += ex.w;
        logits4[p] = ex;
    }
    #pragma unroll
    for (int q = 0; q < 4; q++) {
        #pragma unroll
        for (int o = 16; o > 0; o >>= 1)
            den[q] += __shfl_xor_sync(0xffffffffu, den[q], o);
    }
    __syncwarp();

    // pass 3: weighted message accumulation
    int h = lane >> 3;  // which head this lane's float4 of the 128-msg belongs to
    float dh = (h == 0) ? den[0] : (h == 1) ? den[1] : (h == 2) ? den[2] : den[3];
    float invh = (end > beg) ? (1.0f / dh) : 0.0f;
    float4 acc = make_float4(0.f, 0.f, 0.f, 0.f);
    for (int p = beg; p < end; p++) {
        int e = sorted[p];
        int s = edge_sources[e];
        float4 ex = logits4[p];
        float exh = (h < 2) ? ((h == 0) ? ex.x : ex.y) : ((h == 2) ? ex.z : ex.w);
        float sc = exh * invh;
        float4 m = ms4[(long)s * 32 + lane];
        acc.x += m.x * sc; acc.y += m.y * sc; acc.z += m.z * sc; acc.w += m.w * sc;
    }
    agg4[(long)tgt * 32 + lane] = acc;
}

// ---------------------------------------------------------------------------
// launch
// ---------------------------------------------------------------------------
extern "C" void kernel_launch(void* const* d_in, const int* in_sizes, int n_in,
                              void* d_out, int out_size) {
    const float* src_f = (const float*)d_in[0];
    const float* tgt_f = (const float*)d_in[1];
    const int*   etgt  = (const int*)d_in[2];
    const int*   esrc  = (const int*)d_in[3];
    const float* Ws    = (const float*)d_in[4];
    const float* bs    = (const float*)d_in[5];
    const float* Wt    = (const float*)d_in[6];
    const float* bt    = (const float*)d_in[7];
    const float* aw    = (const float*)d_in[8];
    const float* Wm    = (const float*)d_in[9];
    const float* bm    = (const float*)d_in[10];
    const float* Wo    = (const float*)d_in[11];
    const float* bo    = (const float*)d_in[12];
    float* out = (float*)d_out;

    int N = in_sizes[0] / EMBED;
    int M = in_sizes[1] / EMBED;
    int E = in_sizes[2];

    // resolve scratch symbol addresses (host-side; no allocation)
    float *p_hs, *p_ht, *p_ms, *p_agg, *p_logits;
    int *p_counts, *p_cursor, *p_offsets, *p_sorted;
    cudaGetSymbolAddress((void**)&p_hs, g_hs);
    cudaGetSymbolAddress((void**)&p_ht, g_ht);
    cudaGetSymbolAddress((void**)&p_ms, g_ms);
    cudaGetSymbolAddress((void**)&p_agg, g_agg);
    cudaGetSymbolAddress((void**)&p_logits, g_logits);
    cudaGetSymbolAddress((void**)&p_counts, g_counts);
    cudaGetSymbolAddress((void**)&p_cursor, g_cursor);
    cudaGetSymbolAddress((void**)&p_offsets, g_offsets);
    cudaGetSymbolAddress((void**)&p_sorted, g_sorted);

    cudaFuncSetAttribute(gemm128_kernel,
                         cudaFuncAttributeMaxDynamicSharedMemorySize,
                         GEMM_SMEM_BYTES);

    // CSR build
    zero2_kernel<<<(M + 255) / 256, 256>>>(p_counts, p_cursor, M);
    hist_kernel<<<(E + 255) / 256, 256>>>(etgt, p_counts, E);
    scan_kernel<<<1, 1024>>>(p_counts, p_offsets, M);
    scatter_kernel<<<(E + 255) / 256, 256>>>(etgt, p_offsets, p_cursor, p_sorted, E);

    // node-level GEMMs
    {
        dim3 g((N + 127) / 128, HHID / 128);
        gemm128_kernel<<<g, 256, GEMM_SMEM_BYTES>>>(src_f, Ws, bs, p_hs, N, HHID);
    }
    {
        dim3 g((M + 127) / 128, HHID / 128);
        gemm128_kernel<<<g, 256, GEMM_SMEM_BYTES>>>(tgt_f, Wt, bt, p_ht, M, HHID);
    }
    {
        dim3 g((N + 127) / 128, 1);
        gemm128_kernel<<<g, 256, GEMM_SMEM_BYTES>>>(src_f, Wm, bm, p_ms, N, EMBED);
    }

    // per-target edge attention (one warp per target)
    {
        int blocks = (M + 7) / 8;
        edge_attn_kernel<<<blocks, 256>>>(p_sorted, p_offsets, esrc,
                                          (const float4*)p_hs,
                                          (const float4*)p_ht,
                                          (const float4*)p_ms,
                                          (const float4*)aw,
                                          (float4*)p_logits,
                                          (float4*)p_agg, M);
    }

    // output projection
    {
        dim3 g((M + 127) / 128, 1);
        gemm128_kernel<<<g, 256, GEMM_SMEM_BYTES>>>(p_agg, Wo, bo, out, M, EMBED);
    }
}

// round 4
// speedup vs baseline: 1.4196x; 1.4196x over previous
#include <cuda_runtime.h>
#include <cuda_bf16.h>
#include <math.h>
#include <stdint.h>

// Problem constants
#define EMBED 128
#define HHID  512
#define MAXN  50000
#define MAXM  50000
#define MAXE  400000

// ---------------------------------------------------------------------------
// Scratch
// ---------------------------------------------------------------------------
__device__ __align__(16) float g_hs[MAXN * HHID];
__device__ __align__(16) float g_ht[MAXM * HHID];
__device__ __align__(16) float g_ms[MAXN * EMBED];
__device__ __align__(16) float g_agg[MAXM * EMBED];
__device__ __align__(16) float g_logits[MAXE * 4];
__device__ int g_counts[MAXM];
__device__ int g_cursor[MAXM];
__device__ int g_offsets[MAXM + 1];
__device__ int g_sorted_src[MAXE];
// per 128-col block: BT_hi[128n][128k] then BT_lo[128n][128k], plain row-major bf16
__device__ __align__(16) __nv_bfloat16 g_wimg_s[4 * 32768];
__device__ __align__(16) __nv_bfloat16 g_wimg_t[4 * 32768];
__device__ __align__(16) __nv_bfloat16 g_wimg_m[32768];
__device__ __align__(16) __nv_bfloat16 g_wimg_o[32768];

// ---------------------------------------------------------------------------
// helpers
// ---------------------------------------------------------------------------
__device__ __forceinline__ uint32_t smem_u32(const void* p) {
    uint32_t a;
    asm("{ .reg .u64 t; cvta.to.shared.u64 t, %1; cvt.u32.u64 %0, t; }" : "=r"(a) : "l"(p));
    return a;
}

__device__ __forceinline__ void ldsm_x4(uint32_t& r0, uint32_t& r1, uint32_t& r2, uint32_t& r3,
                                        uint32_t addr) {
    asm volatile("ldmatrix.sync.aligned.m8n8.x4.shared.b16 {%0,%1,%2,%3}, [%4];"
                 : "=r"(r0), "=r"(r1), "=r"(r2), "=r"(r3) : "r"(addr));
}

__device__ __forceinline__ void mma_bf16(float* d, const uint32_t* a, uint32_t b0, uint32_t b1) {
    asm volatile("mma.sync.aligned.m16n8k16.row.col.f32.bf16.bf16.f32 "
                 "{%0,%1,%2,%3}, {%4,%5,%6,%7}, {%8,%9}, {%0,%1,%2,%3};"
                 : "+f"(d[0]), "+f"(d[1]), "+f"(d[2]), "+f"(d[3])
                 : "r"(a[0]), "r"(a[1]), "r"(a[2]), "r"(a[3]), "r"(b0), "r"(b1));
}

// ---------------------------------------------------------------------------
// weight conversion -> BT (n-major) hi/lo bf16 images
// ---------------------------------------------------------------------------
__global__ void wconv_kernel(const float* __restrict__ W, __nv_bfloat16* __restrict__ img, int ncols) {
    int i = blockIdx.x * 256 + threadIdx.x;
    int total = 128 * ncols;
    if (i >= total) return;
    int k = i / ncols, c = i - k * ncols;
    int nb = c >> 7, n = c & 127;
    float x = W[i];
    __nv_bfloat16 h = __float2bfloat16(x);
    __nv_bfloat16 l = __float2bfloat16(x - __bfloat162float(h));
    __nv_bfloat16* base = img + (size_t)nb * 32768;
    base[n * 128 + k] = h;
    base[16384 + n * 128 + k] = l;
}

// ---------------------------------------------------------------------------
// HMMA GEMM: C[rows, ncols] = A[rows,128] @ B[128,ncols] + bias
// bf16x3 split (hi*hi + hi*lo + lo*hi), fp32 accumulate.
// CTA: 128x128 tile, 256 threads (8 warps), warp tile 32x64.
// ---------------------------------------------------------------------------
#define SMS 136                       // smem row stride in bf16 (272 B)
#define SM_TILE (128 * SMS)           // elements per tile image
#define TCG_SMEM_BYTES (4 * SM_TILE * 2)

__global__ void __launch_bounds__(256, 1)
tc_gemm_kernel(const float* __restrict__ A, const __nv_bfloat16* __restrict__ Bimg,
               const float* __restrict__ bias, float* __restrict__ C,
               int rows, int ncols) {
    extern __shared__ __align__(16) __nv_bfloat16 sm[];
    __nv_bfloat16* sAh = sm;
    __nv_bfloat16* sAl = sm + SM_TILE;
    __nv_bfloat16* sBh = sm + 2 * SM_TILE;
    __nv_bfloat16* sBl = sm + 3 * SM_TILE;

    int tid = threadIdx.x, wid = tid >> 5, lane = tid & 31;
    int row0 = blockIdx.x * 128, col0 = blockIdx.y * 128;

    // ---- load B tile (pre-converted BT hi/lo), pad stride ----
    {
        const uint4* src = (const uint4*)(Bimg + (size_t)blockIdx.y * 32768);
        for (int idx = tid; idx < 2048; idx += 256) {
            int n = idx >> 4, k8 = (idx & 15);
            uint4 vh = src[idx];
            uint4 vl = src[2048 + idx];
            *(uint4*)(sBh + n * SMS + k8 * 8) = vh;
            *(uint4*)(sBl + n * SMS + k8 * 8) = vl;
        }
    }
    // ---- load + split-convert A tile ----
    for (int idx = tid; idx < 4096; idx += 256) {
        int r = idx >> 5, k0 = (idx & 31) * 4;
        float4 v = make_float4(0.f, 0.f, 0.f, 0.f);
        int gr = row0 + r;
        if (gr < rows) v = *(const float4*)(A + (size_t)gr * 128 + k0);
        uint32_t h01, h23;
        asm("cvt.rn.satfinite.bf16x2.f32 %0, %1, %2;" : "=r"(h01) : "f"(v.y), "f"(v.x));
        asm("cvt.rn.satfinite.bf16x2.f32 %0, %1, %2;" : "=r"(h23) : "f"(v.w), "f"(v.z));
        float r0f = v.x - __uint_as_float(h01 << 16);
        float r1f = v.y - __uint_as_float(h01 & 0xffff0000u);
        float r2f = v.z - __uint_as_float(h23 << 16);
        float r3f = v.w - __uint_as_float(h23 & 0xffff0000u);
        uint32_t l01, l23;
        asm("cvt.rn.satfinite.bf16x2.f32 %0, %1, %2;" : "=r"(l01) : "f"(r1f), "f"(r0f));
        asm("cvt.rn.satfinite.bf16x2.f32 %0, %1, %2;" : "=r"(l23) : "f"(r3f), "f"(r2f));
        *(uint2*)(sAh + r * SMS + k0) = make_uint2(h01, h23);
        *(uint2*)(sAl + r * SMS + k0) = make_uint2(l01, l23);
    }
    __syncthreads();

    // ---- warp tiling: warp_m = wid&3 (32 rows), warp_n = wid>>2 (64 cols) ----
    int wm = (wid & 3) * 32;
    int wn = (wid >> 2) * 64;

    float acc[2][8][4];
    #pragma unroll
    for (int i = 0; i < 2; i++)
        #pragma unroll
        for (int j = 0; j < 8; j++)
            #pragma unroll
            for (int q = 0; q < 4; q++) acc[i][j][q] = 0.f;

    // A frag addr: row = wm + mt*16 + (lane&15), col = k + (lane>>4)*8
    uint32_t a_base_h = smem_u32(sAh) + (((wm + (lane & 15)) * SMS + ((lane >> 4) << 3)) << 1);
    uint32_t a_base_l = a_base_h + (uint32_t)(SM_TILE << 1);
    // B frag addr: row n = wn + np*16 + ((lane&16)>>1) + (lane&7), col = k + (lane&8)
    uint32_t b_row = (uint32_t)(wn + ((lane & 16) >> 1) + (lane & 7));
    uint32_t b_base_h = smem_u32(sBh) + ((b_row * SMS + (lane & 8)) << 1);
    uint32_t b_base_l = b_base_h + (uint32_t)(SM_TILE << 1);

    #pragma unroll
    for (int ks = 0; ks < 8; ks++) {
        uint32_t koff = (uint32_t)(ks * 16 * 2);
        uint32_t ah[2][4], al[2][4];
        #pragma unroll
        for (int mt = 0; mt < 2; mt++) {
            uint32_t off = koff + (uint32_t)((mt * 16 * SMS) << 1);
            ldsm_x4(ah[mt][0], ah[mt][1], ah[mt][2], ah[mt][3], a_base_h + off);
            ldsm_x4(al[mt][0], al[mt][1], al[mt][2], al[mt][3], a_base_l + off);
        }
        #pragma unroll
        for (int np = 0; np < 4; np++) {
            uint32_t off = koff + (uint32_t)((np * 16 * SMS) << 1);
            uint32_t bh[4], bl[4];
            ldsm_x4(bh[0], bh[1], bh[2], bh[3], b_base_h + off);
            ldsm_x4(bl[0], bl[1], bl[2], bl[3], b_base_l + off);
            #pragma unroll
            for (int mt = 0; mt < 2; mt++) {
                mma_bf16(acc[mt][np * 2 + 0], ah[mt], bh[0], bh[1]);
                mma_bf16(acc[mt][np * 2 + 1], ah[mt], bh[2], bh[3]);
                mma_bf16(acc[mt][np * 2 + 0], ah[mt], bl[0], bl[1]);
                mma_bf16(acc[mt][np * 2 + 1], ah[mt], bl[2], bl[3]);
                mma_bf16(acc[mt][np * 2 + 0], al[mt], bh[0], bh[1]);
                mma_bf16(acc[mt][np * 2 + 1], al[mt], bh[2], bh[3]);
            }
        }
    }

    // ---- epilogue ----
    int g = lane >> 2, tg = lane & 3;
    #pragma unroll
    for (int mt = 0; mt < 2; mt++) {
        int r_lo = row0 + wm + mt * 16 + g;
        int r_hi = r_lo + 8;
        #pragma unroll
        for (int nt = 0; nt < 8; nt++) {
            int gc = col0 + wn + nt * 8 + tg * 2;
            float b0 = bias[gc], b1 = bias[gc + 1];
            if (r_lo < rows) {
                float2 o = make_float2(acc[mt][nt][0] + b0, acc[mt][nt][1] + b1);
                *(float2*)(C + (size_t)r_lo * ncols + gc) = o;
            }
            if (r_hi < rows) {
                float2 o = make_float2(acc[mt][nt][2] + b0, acc[mt][nt][3] + b1);
                *(float2*)(C + (size_t)r_hi * ncols + gc) = o;
            }
        }
    }
}

// ---------------------------------------------------------------------------
// CSR build
// ---------------------------------------------------------------------------
__global__ void zero2_kernel(int* a, int* b, int n) {
    int i = blockIdx.x * blockDim.x + threadIdx.x;
    if (i < n) { a[i] = 0; b[i] = 0; }
}
__global__ void hist_kernel(const int* __restrict__ etgt, int* __restrict__ counts, int E) {
    int i = blockIdx.x * blockDim.x + threadIdx.x;
    if (i < E) atomicAdd(&counts[etgt[i]], 1);
}
__global__ void scan_kernel(const int* __restrict__ counts, int* __restrict__ offsets, int M) {
    __shared__ int wsum[32];
    int t = threadIdx.x;
    int chunk = (M + 1023) >> 10;
    int b0 = t * chunk, b1 = b0 + chunk;
    if (b0 > M) b0 = M;
    if (b1 > M) b1 = M;
    int s = 0;
    for (int i = b0; i < b1; i++) s += counts[i];
    int lane = t & 31, w = t >> 5;
    int v = s;
    #pragma unroll
    for (int o = 1; o < 32; o <<= 1) { int x = __shfl_up_sync(0xffffffffu, v, o); if (lane >= o) v += x; }
    if (lane == 31) wsum[w] = v;
    __syncthreads();
    if (w == 0) {
        int x = wsum[lane];
        #pragma unroll
        for (int o = 1; o < 32; o <<= 1) { int y = __shfl_up_sync(0xffffffffu, x, o); if (lane >= o) x += y; }
        wsum[lane] = x;
    }
    __syncthreads();
    int run = v - s + (w > 0 ? wsum[w - 1] : 0);
    for (int i = b0; i < b1; i++) { offsets[i] = run; run += counts[i]; }
    if (t == 1023) offsets[M] = run;
}
__global__ void scatter_kernel(const int* __restrict__ etgt, const int* __restrict__ esrc,
                               const int* __restrict__ offsets, int* __restrict__ cursor,
                               int* __restrict__ ssrc, int E) {
    int i = blockIdx.x * blockDim.x + threadIdx.x;
    if (i < E) {
        int tg = etgt[i];
        int pos = offsets[tg] + atomicAdd(&cursor[tg], 1);
        ssrc[pos] = esrc[i];
    }
}

// ---------------------------------------------------------------------------
// Edge attention: one warp per target
// ---------------------------------------------------------------------------
__device__ __forceinline__ float gelu_exact(float x) {
    return 0.5f * x * (1.0f + erff(x * 0.70710678118654752440f));
}

__global__ void __launch_bounds__(256)
edge_attn_kernel(const int* __restrict__ sorted_src,
                 const int* __restrict__ offsets,
                 const float4* __restrict__ hs4,
                 const float4* __restrict__ ht4,
                 const float4* __restrict__ ms4,
                 const float4* __restrict__ aw4,
                 float4* __restrict__ logits4,
                 float4* __restrict__ agg4,
                 int M) {
    int warp = (blockIdx.x * blockDim.x + threadIdx.x) >> 5;
    int lane = threadIdx.x & 31;
    if (warp >= M) return;
    int tgt = warp;
    int beg = offsets[tgt], end = offsets[tgt + 1];

    float4 htv[4], aw[4];
    #pragma unroll
    for (int q = 0; q < 4; q++) {
        htv[q] = ht4[(size_t)tgt * 128 + lane + 32 * q];
        aw[q] = aw4[q * 32 + lane];
    }

    float mx[4] = {-3.4e38f, -3.4e38f, -3.4e38f, -3.4e38f};

    for (int p = beg; p < end; p++) {
        int s = sorted_src[p];
        float part[4];
        #pragma unroll
        for (int q = 0; q < 4; q++) {
            float4 h = hs4[(size_t)s * 128 + lane + 32 * q];
            float x0 = gelu_exact(h.x + htv[q].x);
            float x1 = gelu_exact(h.y + htv[q].y);
            float x2 = gelu_exact(h.z + htv[q].z);
            float x3 = gelu_exact(h.w + htv[q].w);
            part[q] = fmaf(x0, aw[q].x, fmaf(x1, aw[q].y, fmaf(x2, aw[q].z, x3 * aw[q].w)));
        }
        #pragma unroll
        for (int q = 0; q < 4; q++) {
            #pragma unroll
            for (int o = 16; o > 0; o >>= 1)
                part[q] += __shfl_xor_sync(0xffffffffu, part[q], o);
            mx[q] = fmaxf(mx[q], part[q]);
        }
        if (lane == 0)
            logits4[p] = make_float4(part[0], part[1], part[2], part[3]);
    }
    __syncwarp();

    float den[4] = {0.f, 0.f, 0.f, 0.f};
    for (int p = beg + lane; p < end; p += 32) {
        float4 lg = logits4[p];
        float4 ex;
        ex.x = __expf(lg.x - mx[0]);
        ex.y = __expf(lg.y - mx[1]);
        ex.z = __expf(lg.z - mx[2]);
        ex.w = __expf(lg.w - mx[3]);
        den[0] += ex.x; den[1] += ex.y; den[2] += ex.z; den[3] += ex.w;
        logits4[p] = ex;
    }
    #pragma unroll
    for (int q = 0; q < 4; q++) {
        #pragma unroll
        for (int o = 16; o > 0; o >>= 1)
            den[q] += __shfl_xor_sync(0xffffffffu, den[q], o);
    }
    __syncwarp();

    int h = lane >> 3;
    float dh = (h == 0) ? den[0] : (h == 1) ? den[1] : (h == 2) ? den[2] : den[3];
    float invh = (end > beg) ? (1.0f / dh) : 0.0f;
    float4 acc = make_float4(0.f, 0.f, 0.f, 0.f);
    for (int p = beg; p < end; p++) {
        int s = sorted_src[p];
        float4 ex = logits4[p];
        float exh = (h < 2) ? ((h == 0) ? ex.x : ex.y) : ((h == 2) ? ex.z : ex.w);
        float sc = exh * invh;
        float4 m = ms4[(size_t)s * 32 + lane];
        acc.x += m.x * sc; acc.y += m.y * sc; acc.z += m.z * sc; acc.w += m.w * sc;
    }
    agg4[(size_t)tgt * 32 + lane] = acc;
}

// ---------------------------------------------------------------------------
// launch
// ---------------------------------------------------------------------------
extern "C" void kernel_launch(void* const* d_in, const int* in_sizes, int n_in,
                              void* d_out, int out_size) {
    const float* src_f = (const float*)d_in[0];
    const float* tgt_f = (const float*)d_in[1];
    const int*   etgt  = (const int*)d_in[2];
    const int*   esrc  = (const int*)d_in[3];
    const float* Ws    = (const float*)d_in[4];
    const float* bs    = (const float*)d_in[5];
    const float* Wt    = (const float*)d_in[6];
    const float* bt    = (const float*)d_in[7];
    const float* aw    = (const float*)d_in[8];
    const float* Wm    = (const float*)d_in[9];
    const float* bm    = (const float*)d_in[10];
    const float* Wo    = (const float*)d_in[11];
    const float* bo    = (const float*)d_in[12];
    float* out = (float*)d_out;

    int N = in_sizes[0] / EMBED;
    int M = in_sizes[1] / EMBED;
    int E = in_sizes[2];

    float *p_hs, *p_ht, *p_ms, *p_agg, *p_logits;
    int *p_counts, *p_cursor, *p_offsets, *p_ssrc;
    __nv_bfloat16 *p_ws, *p_wt, *p_wm, *p_wo;
    cudaGetSymbolAddress((void**)&p_hs, g_hs);
    cudaGetSymbolAddress((void**)&p_ht, g_ht);
    cudaGetSymbolAddress((void**)&p_ms, g_ms);
    cudaGetSymbolAddress((void**)&p_agg, g_agg);
    cudaGetSymbolAddress((void**)&p_logits, g_logits);
    cudaGetSymbolAddress((void**)&p_counts, g_counts);
    cudaGetSymbolAddress((void**)&p_cursor, g_cursor);
    cudaGetSymbolAddress((void**)&p_offsets, g_offsets);
    cudaGetSymbolAddress((void**)&p_ssrc, g_sorted_src);
    cudaGetSymbolAddress((void**)&p_ws, g_wimg_s);
    cudaGetSymbolAddress((void**)&p_wt, g_wimg_t);
    cudaGetSymbolAddress((void**)&p_wm, g_wimg_m);
    cudaGetSymbolAddress((void**)&p_wo, g_wimg_o);

    cudaFuncSetAttribute(tc_gemm_kernel,
                         cudaFuncAttributeMaxDynamicSharedMemorySize, TCG_SMEM_BYTES);

    // launches ordered so ncu's "-s 5 -c 1" capture lands on the big hs GEMM
    zero2_kernel<<<(M + 255) / 256, 256>>>(p_counts, p_cursor, M);                 // 0
    wconv_kernel<<<(128 * HHID + 255) / 256, 256>>>(Ws, p_ws, HHID);               // 1
    wconv_kernel<<<(128 * HHID + 255) / 256, 256>>>(Wt, p_wt, HHID);               // 2
    wconv_kernel<<<(128 * EMBED + 255) / 256, 256>>>(Wm, p_wm, EMBED);             // 3
    wconv_kernel<<<(128 * EMBED + 255) / 256, 256>>>(Wo, p_wo, EMBED);             // 4
    {
        dim3 g((N + 127) / 128, HHID / 128);                                       // 5 (captured)
        tc_gemm_kernel<<<g, 256, TCG_SMEM_BYTES>>>(src_f, p_ws, bs, p_hs, N, HHID);
    }
    {
        dim3 g((M + 127) / 128, HHID / 128);                                       // 6
        tc_gemm_kernel<<<g, 256, TCG_SMEM_BYTES>>>(tgt_f, p_wt, bt, p_ht, M, HHID);
    }
    {
        dim3 g((N + 127) / 128, 1);                                                // 7
        tc_gemm_kernel<<<g, 256, TCG_SMEM_BYTES>>>(src_f, p_wm, bm, p_ms, N, EMBED);
    }
    hist_kernel<<<(E + 255) / 256, 256>>>(etgt, p_counts, E);                      // 8
    scan_kernel<<<1, 1024>>>(p_counts, p_offsets, M);                              // 9
    scatter_kernel<<<(E + 255) / 256, 256>>>(etgt, esrc, p_offsets, p_cursor, p_ssrc, E); // 10
    {
        int blocks = (M + 7) / 8;                                                  // 11
        edge_attn_kernel<<<blocks, 256>>>(p_ssrc, p_offsets,
                                          (const float4*)p_hs, (const float4*)p_ht,
                                          (const float4*)p_ms, (const float4*)aw,
                                          (float4*)p_logits, (float4*)p_agg, M);
    }
    {
        dim3 g((M + 127) / 128, 1);                                                // 12
        tc_gemm_kernel<<<g, 256, TCG_SMEM_BYTES>>>(p_agg, p_wo, bo, out, M, EMBED);
    }
}